// round 7
// baseline (speedup 1.0000x reference)
#include <cuda_runtime.h>

// out = y where 0 < y <= 1 else 0, y = x * w[col] + b[col]
// x: [8192, 4096] f32, w/b: [4096] f32. HBM-bound elementwise.
// R7: sm_100a 256-bit vector ld/st (v8.f32). R2 structure: flat grid,
//     chunk == one D row, front-batched streaming x reads, JIT w/b reads.

#define D_V8 512              // 4096 / 8
#define ITEMS 2               // v8 chunks per thread (= 16 floats, same as R2)
#define THREADS 256
#define CHUNK (THREADS * ITEMS)   // 512 == D_V8 -> col(i) = t + i*256

struct alignas(32) f8 { float v[8]; };

__device__ __forceinline__ f8 ldg_v8_cs(const f8* p) {
    f8 r;
    asm volatile("ld.global.cs.v8.f32 {%0,%1,%2,%3,%4,%5,%6,%7}, [%8];"
        : "=f"(r.v[0]), "=f"(r.v[1]), "=f"(r.v[2]), "=f"(r.v[3]),
          "=f"(r.v[4]), "=f"(r.v[5]), "=f"(r.v[6]), "=f"(r.v[7])
        : "l"(p));
    return r;
}

__device__ __forceinline__ f8 ldg_v8_nc(const f8* p) {
    f8 r;
    asm volatile("ld.global.nc.v8.f32 {%0,%1,%2,%3,%4,%5,%6,%7}, [%8];"
        : "=f"(r.v[0]), "=f"(r.v[1]), "=f"(r.v[2]), "=f"(r.v[3]),
          "=f"(r.v[4]), "=f"(r.v[5]), "=f"(r.v[6]), "=f"(r.v[7])
        : "l"(p));
    return r;
}

__device__ __forceinline__ void stg_v8_cs(f8* p, const f8& r) {
    asm volatile("st.global.cs.v8.f32 [%0], {%1,%2,%3,%4,%5,%6,%7,%8};"
        :: "l"(p),
           "f"(r.v[0]), "f"(r.v[1]), "f"(r.v[2]), "f"(r.v[3]),
           "f"(r.v[4]), "f"(r.v[5]), "f"(r.v[6]), "f"(r.v[7])
        : "memory");
}

__global__ void __launch_bounds__(THREADS)
gegate_kernel(const f8* __restrict__ x,
              const f8* __restrict__ w,
              const f8* __restrict__ b,
              f8* __restrict__ out)
{
    const int t = threadIdx.x;
    const int base = blockIdx.x * CHUNK + t;

    // Front-batched streaming reads: 2 independent 256-bit DRAM loads in flight.
    f8 xv[ITEMS];
    #pragma unroll
    for (int i = 0; i < ITEMS; i++)
        xv[i] = ldg_v8_cs(&x[base + i * THREADS]);

    #pragma unroll
    for (int i = 0; i < ITEMS; i++) {
        const int col = t + i * THREADS;   // chunk == D_V8
        f8 wv = ldg_v8_nc(&w[col]);
        f8 bv = ldg_v8_nc(&b[col]);
        f8 y;
        #pragma unroll
        for (int k = 0; k < 8; k++) {
            float v = fmaf(xv[i].v[k], wv.v[k], bv.v[k]);
            y.v[k] = (v > 0.0f && v <= 1.0f) ? v : 0.0f;
        }
        stg_v8_cs(&out[base + i * THREADS], y);
    }
}

extern "C" void kernel_launch(void* const* d_in, const int* in_sizes, int n_in,
                              void* d_out, int out_size)
{
    const f8* x = (const f8*)d_in[0];
    const f8* w = (const f8*)d_in[1];
    const f8* b = (const f8*)d_in[2];
    f8* out = (f8*)d_out;

    int n_v8 = out_size / 8;              // 4194304
    int blocks = n_v8 / CHUNK;            // 8192 exactly

    gegate_kernel<<<blocks, THREADS>>>(x, w, b, out);
}